// round 12
// baseline (speedup 1.0000x reference)
#include <cuda_runtime.h>
#include <cuda_fp16.h>
#include <cstdint>

// ---------------- problem constants ----------------
#define NTOK      4096
#define BATCH     2
#define MROWS     8192
#define NPOS      4095
#define SCALE_Q   0.125f
#define QKVN      1536

// ---------------- scratch ----------------
__device__ __half g_xh   [MROWS * 512];
__device__ float  g_q    [MROWS * 512];          // q (f32), dense
__device__ __half g_zh   [MROWS * 512];          // attention out (f16)
__device__ __half g_wqkvt[QKVN * 512];
__device__ __half g_wot  [512 * 512];
__device__ float2 g_ktp  [16 * 32 * NTOK];       // k transposed, pair-packed [bh][dpair][token]
__device__ float2 g_vtp  [16 * 32 * NTOK];       // v transposed, pair-packed

// ---------------- helpers ----------------
__device__ __forceinline__ uint32_t smem_u32(const void* p) {
    uint32_t a;
    asm("{ .reg .u64 t; cvta.to.shared.u64 t, %1; cvt.u32.u64 %0, t; }" : "=r"(a) : "l"(p));
    return a;
}
__device__ __forceinline__ void cp16(uint32_t dst, const void* src) {
    asm volatile("cp.async.cg.shared.global [%0], [%1], 16;" :: "r"(dst), "l"(src));
}
__device__ __forceinline__ void ldsm4(uint32_t& r0, uint32_t& r1, uint32_t& r2, uint32_t& r3, uint32_t a) {
    asm volatile("ldmatrix.sync.aligned.m8n8.x4.shared.b16 {%0,%1,%2,%3}, [%4];"
                 : "=r"(r0), "=r"(r1), "=r"(r2), "=r"(r3) : "r"(a));
}
__device__ __forceinline__ void mma_f16(float& d0, float& d1, float& d2, float& d3,
                                        uint32_t a0, uint32_t a1, uint32_t a2, uint32_t a3,
                                        uint32_t b0, uint32_t b1) {
    asm volatile(
        "mma.sync.aligned.m16n8k16.row.col.f32.f16.f16.f32 "
        "{%0,%1,%2,%3}, {%4,%5,%6,%7}, {%8,%9}, {%0,%1,%2,%3};"
        : "+f"(d0), "+f"(d1), "+f"(d2), "+f"(d3)
        : "r"(a0), "r"(a1), "r"(a2), "r"(a3), "r"(b0), "r"(b1));
}

// ---------------- fused prologue: x->f16 + all three weight transposes ----------------
__device__ __forceinline__ void do_transpose(const float* __restrict__ in, __half* __restrict__ out,
                                             int R, int C, int bx, int by, int tx, int ty,
                                             float (*t)[33])
{
    const int x0 = bx * 32, y0 = by * 32;
    #pragma unroll
    for (int j = 0; j < 32; j += 8)
        t[ty + j][tx] = in[(long)(y0 + ty + j) * C + x0 + tx];
    __syncthreads();
    #pragma unroll
    for (int j = 0; j < 32; j += 8)
        out[(long)(x0 + ty + j) * R + y0 + tx] = __float2half(t[tx][ty + j]);
}

__global__ __launch_bounds__(256)
void prep_kernel(const float* __restrict__ x, const float* __restrict__ Wq,
                 const float* __restrict__ Wkv, const float* __restrict__ Wo)
{
    __shared__ float t[32][33];
    const int blk = blockIdx.x;
    const int tid = threadIdx.x;
    if (blk < 4096) {
        const long i = ((long)blk * 256 + tid) * 4;
        float4 v = *(const float4*)(x + i);
        *(__half2*)(g_xh + i)     = __floats2half2_rn(v.x, v.y);
        *(__half2*)(g_xh + i + 2) = __floats2half2_rn(v.z, v.w);
        return;
    }
    const int tx = tid & 31, ty = tid >> 5;
    if (blk < 4096 + 256) {
        const int z = blk - 4096;
        do_transpose(Wq, g_wqkvt, 512, 512, z & 15, z >> 4, tx, ty, t);
    } else if (blk < 4096 + 256 + 512) {
        const int z = blk - 4096 - 256;
        do_transpose(Wkv, g_wqkvt + 512 * 512, 512, 1024, z & 31, z >> 5, tx, ty, t);
    } else {
        const int z = blk - 4096 - 256 - 512;
        do_transpose(Wo, g_wot, 512, 512, z & 15, z >> 4, tx, ty, t);
    }
}

// ---------------- f16 mma GEMM: CTA 128x128, 4 warps (64x64 warp tile), 4-stage ----------------
// EPI 0: C = acc + bias (f32, GEMM2)
// EPI 1: QKV routing epilogue — q -> g_q, k/v -> pair-packed transposed g_ktp/g_vtp
#define HSTAGE 12288
#define HSMEM  (4 * HSTAGE)

template<int EPI>
__global__ __launch_bounds__(128)
void tgemm_h(const __half* __restrict__ A, const __half* __restrict__ Bt,
             const float* __restrict__ bias, float* __restrict__ C, int N)
{
    extern __shared__ char sm[];
    const uint32_t sbase = smem_u32(sm);

    const int tid  = threadIdx.x;
    const int lane = tid & 31;
    const int wid  = tid >> 5;
    const int wm   = wid >> 1;
    const int wn   = wid & 1;

    const int row0 = blockIdx.y * 128;
    const int col0 = blockIdx.x * 128;

    const __half* Ap = A  + (long)(row0 + tid) * 512;
    const __half* Bp = Bt + (long)(col0 + tid) * 512;
    const uint32_t dRow = (uint32_t)(tid * 48);

    auto issue_stage = [&](int kk, int s) {
        const uint32_t so = sbase + (uint32_t)s * HSTAGE;
        const long ko = (long)kk * 16;
        cp16(so + dRow,              Ap + ko);
        cp16(so + dRow + 16,         Ap + ko + 8);
        cp16(so + 6144u + dRow,      Bp + ko);
        cp16(so + 6144u + dRow + 16, Bp + ko + 8);
        asm volatile("cp.async.commit_group;" ::: "memory");
    };

    uint32_t aoff[4], boff[4];
    #pragma unroll
    for (int mt = 0; mt < 4; mt++)
        aoff[mt] = (uint32_t)((wm * 64 + mt * 16 + ((lane >> 3) & 1) * 8 + (lane & 7)) * 48
                              + (lane >> 4) * 16);
    #pragma unroll
    for (int nt = 0; nt < 4; nt++)
        boff[nt] = (uint32_t)((wn * 64 + nt * 16 + ((lane >> 4) & 1) * 8 + (lane & 7)) * 48
                              + ((lane >> 3) & 1) * 16) + 6144u;

    float acc[4][8][4];
    #pragma unroll
    for (int mt = 0; mt < 4; mt++)
        #pragma unroll
        for (int nb = 0; nb < 8; nb++)
            #pragma unroll
            for (int e = 0; e < 4; e++) acc[mt][nb][e] = 0.f;

    issue_stage(0, 0);
    issue_stage(1, 1);
    issue_stage(2, 2);

    for (int kk = 0; kk < 32; kk++) {
        asm volatile("cp.async.wait_group 2;" ::: "memory");
        __syncthreads();

        if (kk + 3 < 32) issue_stage(kk + 3, (kk + 3) & 3);
        else asm volatile("cp.async.commit_group;" ::: "memory");

        const uint32_t sa = sbase + (uint32_t)(kk & 3) * HSTAGE;

        uint32_t af[4][4], bfr[4][4];
        #pragma unroll
        for (int mt = 0; mt < 4; mt++)
            ldsm4(af[mt][0], af[mt][1], af[mt][2], af[mt][3], sa + aoff[mt]);
        #pragma unroll
        for (int nt = 0; nt < 4; nt++)
            ldsm4(bfr[nt][0], bfr[nt][1], bfr[nt][2], bfr[nt][3], sa + boff[nt]);

        #pragma unroll
        for (int mt = 0; mt < 4; mt++)
            #pragma unroll
            for (int nt = 0; nt < 4; nt++) {
                mma_f16(acc[mt][2*nt][0], acc[mt][2*nt][1], acc[mt][2*nt][2], acc[mt][2*nt][3],
                        af[mt][0], af[mt][1], af[mt][2], af[mt][3],
                        bfr[nt][0], bfr[nt][1]);
                mma_f16(acc[mt][2*nt+1][0], acc[mt][2*nt+1][1], acc[mt][2*nt+1][2], acc[mt][2*nt+1][3],
                        af[mt][0], af[mt][1], af[mt][2], af[mt][3],
                        bfr[nt][2], bfr[nt][3]);
            }
    }

    const int r  = lane >> 2;
    const int cp = (lane & 3) * 2;

    if (EPI == 0) {
        #pragma unroll
        for (int mt = 0; mt < 4; mt++) {
            #pragma unroll
            for (int nb = 0; nb < 8; nb++) {
                const int cc = col0 + wn * 64 + nb * 8 + cp;
                const float bx = bias[cc], by = bias[cc + 1];
                const long r1 = row0 + wm * 64 + mt * 16 + r;
                *(float2*)(C + r1 * N + cc)       = make_float2(acc[mt][nb][0] + bx, acc[mt][nb][1] + by);
                *(float2*)(C + (r1 + 8) * N + cc) = make_float2(acc[mt][nb][2] + bx, acc[mt][nb][3] + by);
            }
        }
    } else {
        const int region = col0 >> 9;            // 0=q, 1=k, 2=v (CTA cols within one region)
        #pragma unroll
        for (int mt = 0; mt < 4; mt++) {
            #pragma unroll
            for (int nb = 0; nb < 8; nb++) {
                const int cc = col0 + wn * 64 + nb * 8 + cp;
                const long r1 = row0 + wm * 64 + mt * 16 + r;
                if (region == 0) {
                    const int qc = cc & 511;
                    *(float2*)(g_q + r1 * 512 + qc)       = make_float2(acc[mt][nb][0], acc[mt][nb][1]);
                    *(float2*)(g_q + (r1 + 8) * 512 + qc) = make_float2(acc[mt][nb][2], acc[mt][nb][3]);
                } else {
                    const int kcol = cc & 511;
                    const int h = kcol >> 6;
                    const int d = kcol & 63;
                    float2* base = (region == 1 ? g_ktp : g_vtp);
                    #pragma unroll
                    for (int half = 0; half < 2; half++) {
                        const long rr = r1 + half * 8;
                        const int b = (int)(rr >> 12);
                        const int tkn = (int)(rr & 4095);
                        base[((long)(((b << 3) | h) * 32 + (d >> 1))) * NTOK + tkn]
                            = make_float2(acc[mt][nb][2 * half], acc[mt][nb][2 * half + 1]);
                    }
                }
            }
        }
    }
}

// ---------------- windowed attention: d-split across 4 warps + fused BOS ----------------
__constant__ int C_DF[14] = {-1,-1,-1,-1,-1,-1,-1,-1,-1, 0, 0, 0, 0, 0};
__constant__ int C_DH[14] = {-1,-1,-1, 0, 0, 0, 1, 1, 1,-1,-1,-1, 0, 0};
__constant__ int C_DW[14] = {-1, 0, 1,-1, 0, 1,-1, 0, 1,-1, 0, 1,-1, 0};

__global__ __launch_bounds__(128, 8)
void attn_kernel()
{
    __shared__ float qs[2112];
    __shared__ float ps[4][15][32];

    const int blk  = blockIdx.x;
    const int tid  = threadIdx.x;

    if (blk == 2048) {     // fused BOS rows: zh[b,0,:] = f16(v(token 0))
        for (int e = tid; e < 1024; e += 128) {
            const int b = e >> 9, t = e & 511;
            const int h = t >> 6, d = t & 63;
            const float2 v = g_vtp[((long)(((b << 3) | h) * 32 + (d >> 1))) * NTOK];
            g_zh[(long)b * NTOK * 512 + t] = __float2half((d & 1) ? v.y : v.x);
        }
        return;
    }

    const int w    = tid >> 5;
    const int lane = tid & 31;
    const int grp  = blk & 127;
    const int bh   = blk >> 7;
    const int b    = bh >> 3;
    const int h    = bh & 7;
    const int i0   = grp * 32;
    const int f    = i0 >> 10;
    const int hh   = (i0 >> 5) & 31;
    const int i    = i0 + lane;

    // ---- stage q (coalesced) ----
    {
        const int r = tid >> 2;
        const int c = (tid & 3) * 16;
        const int tk = min(i0 + r, NPOS - 1) + 1;
        const float* src = g_q + (long)(b * NTOK + tk) * 512 + h * 64 + c;
        #pragma unroll
        for (int j = 0; j < 16; j += 4) {
            float4 v = *(const float4*)(src + j);
            qs[r * 65 + c + j]     = v.x;
            qs[r * 65 + c + j + 1] = v.y;
            qs[r * 65 + c + j + 2] = v.z;
            qs[r * 65 + c + j + 3] = v.w;
        }
    }
    __syncthreads();

    float q[16];
    #pragma unroll
    for (int j = 0; j < 16; j++) q[j] = qs[lane * 65 + w * 16 + j] * SCALE_Q;

    const float2* ktb = g_ktp + ((long)bh * 32 + w * 8) * NTOK;
    const float2* vtb = g_vtp + ((long)bh * 32 + w * 8) * NTOK;

    // ---- partial sims (pair-packed loads) ----
    {   // BOS
        float a0 = 0.f, a1 = 0.f;
        #pragma unroll
        for (int dp = 0; dp < 8; dp++) {
            const float2 kk = ktb[(long)dp * NTOK];
            a0 += q[2 * dp]     * kk.x;
            a1 += q[2 * dp + 1] * kk.y;
        }
        ps[w][0][lane] = a0 + a1;
    }
    #pragma unroll
    for (int s = 0; s < 14; s++) {
        const int df = C_DF[s], dh = C_DH[s], dw = C_DW[s];
        const int off = df * 1024 + dh * 32 + dw;
        const int warp_ok = (f + df >= 0) && ((unsigned)(hh + dh) < 32u);
        float acc = 0.f;
        if (warp_ok) {
            const int t = min(max(i + off, 0), NPOS - 1) + 1;
            const float2* kp = ktb + t;
            float a0 = 0.f, a1 = 0.f;
            #pragma unroll
            for (int dp = 0; dp < 8; dp++) {
                const float2 kk = kp[(long)dp * NTOK];
                a0 += q[2 * dp]     * kk.x;
                a1 += q[2 * dp + 1] * kk.y;
            }
            acc = a0 + a1;
        }
        ps[w][s + 1][lane] = acc;
    }
    __syncthreads();

    // ---- combine + softmax (each warp redundantly) ----
    const float NEG_INF = __int_as_float(0xff800000);
    float p[15];
    {
        p[0] = ps[0][0][lane] + ps[1][0][lane] + ps[2][0][lane] + ps[3][0][lane];
        #pragma unroll
        for (int s = 0; s < 14; s++) {
            const int df = C_DF[s], dh = C_DH[s], dw = C_DW[s];
            const int ok = (f + df >= 0) && ((unsigned)(hh + dh) < 32u)
                        && ((unsigned)(lane + dw) < 32u) && (i < NPOS);
            p[s + 1] = ok ? (ps[0][s + 1][lane] + ps[1][s + 1][lane]
                           + ps[2][s + 1][lane] + ps[3][s + 1][lane]) : NEG_INF;
        }
        float m = p[0];
        #pragma unroll
        for (int s = 1; s < 15; s++) m = fmaxf(m, p[s]);
        float den = 0.f;
        #pragma unroll
        for (int s = 0; s < 15; s++) { p[s] = __expf(p[s] - m); den += p[s]; }
        const float inv = 1.f / den;
        #pragma unroll
        for (int s = 0; s < 15; s++) p[s] *= inv;
    }

    // ---- PV: warp computes its 16-d slice (tok recomputed) ----
    float o[16];
    #pragma unroll
    for (int d = 0; d < 16; d++) o[d] = 0.f;
    {   // BOS
        const float pw = p[0];
        #pragma unroll
        for (int dp = 0; dp < 8; dp++) {
            const float2 vv = vtb[(long)dp * NTOK];
            o[2 * dp]     += pw * vv.x;
            o[2 * dp + 1] += pw * vv.y;
        }
    }
    #pragma unroll
    for (int s = 0; s < 14; s++) {
        const int df = C_DF[s], dh = C_DH[s], dw = C_DW[s];
        const int warp_ok = (f + df >= 0) && ((unsigned)(hh + dh) < 32u);
        if (warp_ok) {
            const int off = df * 1024 + dh * 32 + dw;
            const int t = min(max(i + off, 0), NPOS - 1) + 1;
            const float pw = p[s + 1];
            const float2* vp = vtb + t;
            #pragma unroll
            for (int dp = 0; dp < 8; dp++) {
                const float2 vv = vp[(long)dp * NTOK];
                o[2 * dp]     += pw * vv.x;
                o[2 * dp + 1] += pw * vv.y;
            }
        }
    }
    __syncthreads();   // qs reads done -> reuse as output staging

    #pragma unroll
    for (int d = 0; d < 16; d++) qs[(w * 16 + d) * 33 + lane] = o[d];
    __syncthreads();

    // ---- coalesced f16 store ----
    {
        const int r = tid >> 2;
        const int c = (tid & 3) * 16;
        const int irow = i0 + r;
        if (irow < NPOS) {
            __half* dst = g_zh + (long)(b * NTOK + irow + 1) * 512 + h * 64 + c;
            #pragma unroll
            for (int j = 0; j < 16; j += 2) {
                const float x0 = qs[(c + j) * 33 + r];
                const float x1 = qs[(c + j + 1) * 33 + r];
                *(__half2*)(dst + j) = __floats2half2_rn(x0, x1);
            }
        }
    }
}

// ---------------- launch ----------------
extern "C" void kernel_launch(void* const* d_in, const int* in_sizes, int n_in,
                              void* d_out, int out_size)
{
    const float* x   = (const float*)d_in[0];
    const float* Wq  = (const float*)d_in[1];
    const float* Wkv = (const float*)d_in[2];
    const float* Wo  = (const float*)d_in[3];
    const float* bo  = (const float*)d_in[4];
    float* out = (float*)d_out;

    __half *xh, *wqkvt, *wot, *zh;
    cudaGetSymbolAddress((void**)&xh,    g_xh);
    cudaGetSymbolAddress((void**)&zh,    g_zh);
    cudaGetSymbolAddress((void**)&wqkvt, g_wqkvt);
    cudaGetSymbolAddress((void**)&wot,   g_wot);

    cudaFuncSetAttribute(tgemm_h<0>, cudaFuncAttributeMaxDynamicSharedMemorySize, HSMEM);
    cudaFuncSetAttribute(tgemm_h<1>, cudaFuncAttributeMaxDynamicSharedMemorySize, HSMEM);

    // 0) fused prologue
    prep_kernel<<<4096 + 256 + 512 + 256, 256>>>(x, Wq, Wkv, Wo);

    // 1) fused QKV projection with routing epilogue (q dense, k/v transposed pair-packed)
    tgemm_h<1><<<dim3(QKVN / 128, MROWS / 128), 128, HSMEM>>>(xh, wqkvt, nullptr, nullptr, QKVN);

    // 2) windowed causal attention + fused BOS rows
    attn_kernel<<<2049, 128>>>();

    // 3) output projection + bias
    tgemm_h<0><<<dim3(512 / 128, MROWS / 128), 128, HSMEM>>>(zh, wot, bo, out, 512);
}

// round 13
// speedup vs baseline: 1.4371x; 1.4371x over previous
#include <cuda_runtime.h>
#include <cuda_fp16.h>
#include <cstdint>

// ---------------- problem constants ----------------
#define NTOK      4096
#define BATCH     2
#define MROWS     8192
#define NPOS      4095
#define SCALE_Q   0.125f
#define QKVN      1536

// ---------------- scratch ----------------
__device__ __half g_xh   [MROWS * 512];
__device__ float  g_q    [MROWS * 512];          // q (f32), dense
__device__ __half g_zh   [MROWS * 512];          // attention out (f16)
__device__ __half g_wqkvt[QKVN * 512];
__device__ __half g_wot  [512 * 512];
__device__ float2 g_ktp  [16 * 32 * NTOK];       // k transposed, pair-packed [bh][dpair][token]
__device__ float2 g_vtp  [16 * 32 * NTOK];       // v transposed, pair-packed

// ---------------- helpers ----------------
__device__ __forceinline__ uint32_t smem_u32(const void* p) {
    uint32_t a;
    asm("{ .reg .u64 t; cvta.to.shared.u64 t, %1; cvt.u32.u64 %0, t; }" : "=r"(a) : "l"(p));
    return a;
}
__device__ __forceinline__ void cp16(uint32_t dst, const void* src) {
    asm volatile("cp.async.cg.shared.global [%0], [%1], 16;" :: "r"(dst), "l"(src));
}
__device__ __forceinline__ void ldsm4(uint32_t& r0, uint32_t& r1, uint32_t& r2, uint32_t& r3, uint32_t a) {
    asm volatile("ldmatrix.sync.aligned.m8n8.x4.shared.b16 {%0,%1,%2,%3}, [%4];"
                 : "=r"(r0), "=r"(r1), "=r"(r2), "=r"(r3) : "r"(a));
}
__device__ __forceinline__ void mma_f16(float& d0, float& d1, float& d2, float& d3,
                                        uint32_t a0, uint32_t a1, uint32_t a2, uint32_t a3,
                                        uint32_t b0, uint32_t b1) {
    asm volatile(
        "mma.sync.aligned.m16n8k16.row.col.f32.f16.f16.f32 "
        "{%0,%1,%2,%3}, {%4,%5,%6,%7}, {%8,%9}, {%0,%1,%2,%3};"
        : "+f"(d0), "+f"(d1), "+f"(d2), "+f"(d3)
        : "r"(a0), "r"(a1), "r"(a2), "r"(a3), "r"(b0), "r"(b1));
}

// ---------------- fused prologue: x->f16 + all three weight transposes ----------------
__device__ __forceinline__ void do_transpose(const float* __restrict__ in, __half* __restrict__ out,
                                             int R, int C, int bx, int by, int tx, int ty,
                                             float (*t)[33])
{
    const int x0 = bx * 32, y0 = by * 32;
    #pragma unroll
    for (int j = 0; j < 32; j += 8)
        t[ty + j][tx] = in[(long)(y0 + ty + j) * C + x0 + tx];
    __syncthreads();
    #pragma unroll
    for (int j = 0; j < 32; j += 8)
        out[(long)(x0 + ty + j) * R + y0 + tx] = __float2half(t[tx][ty + j]);
}

__global__ __launch_bounds__(256)
void prep_kernel(const float* __restrict__ x, const float* __restrict__ Wq,
                 const float* __restrict__ Wkv, const float* __restrict__ Wo)
{
    __shared__ float t[32][33];
    const int blk = blockIdx.x;
    const int tid = threadIdx.x;
    if (blk < 4096) {
        const long i = ((long)blk * 256 + tid) * 4;
        float4 v = *(const float4*)(x + i);
        *(__half2*)(g_xh + i)     = __floats2half2_rn(v.x, v.y);
        *(__half2*)(g_xh + i + 2) = __floats2half2_rn(v.z, v.w);
        return;
    }
    const int tx = tid & 31, ty = tid >> 5;
    if (blk < 4096 + 256) {
        const int z = blk - 4096;
        do_transpose(Wq, g_wqkvt, 512, 512, z & 15, z >> 4, tx, ty, t);
    } else if (blk < 4096 + 256 + 512) {
        const int z = blk - 4096 - 256;
        do_transpose(Wkv, g_wqkvt + 512 * 512, 512, 1024, z & 31, z >> 5, tx, ty, t);
    } else {
        const int z = blk - 4096 - 256 - 512;
        do_transpose(Wo, g_wot, 512, 512, z & 15, z >> 4, tx, ty, t);
    }
}

// ================= GEMM1: QKV projection, CTA 128x128, routing epilogue =================
// q -> g_q (dense f32); k/v -> smem-transposed, coalesced pair-packed g_ktp/g_vtp
#define HSTAGE 12288
#define HSMEM  (4 * HSTAGE)     // 49152; transpose staging needs 128*67*4 = 34304 (fits)

__global__ __launch_bounds__(128)
void tgemm_qkv(const __half* __restrict__ A, const __half* __restrict__ Bt)
{
    extern __shared__ char sm[];
    const uint32_t sbase = smem_u32(sm);

    const int tid  = threadIdx.x;
    const int lane = tid & 31;
    const int wid  = tid >> 5;
    const int wm   = wid >> 1;
    const int wn   = wid & 1;

    const int row0 = blockIdx.y * 128;
    const int col0 = blockIdx.x * 128;

    const __half* Ap = A  + (long)(row0 + tid) * 512;
    const __half* Bp = Bt + (long)(col0 + tid) * 512;
    const uint32_t dRow = (uint32_t)(tid * 48);

    auto issue_stage = [&](int kk, int s) {
        const uint32_t so = sbase + (uint32_t)s * HSTAGE;
        const long ko = (long)kk * 16;
        cp16(so + dRow,              Ap + ko);
        cp16(so + dRow + 16,         Ap + ko + 8);
        cp16(so + 6144u + dRow,      Bp + ko);
        cp16(so + 6144u + dRow + 16, Bp + ko + 8);
        asm volatile("cp.async.commit_group;" ::: "memory");
    };

    uint32_t aoff[4], boff[4];
    #pragma unroll
    for (int mt = 0; mt < 4; mt++)
        aoff[mt] = (uint32_t)((wm * 64 + mt * 16 + ((lane >> 3) & 1) * 8 + (lane & 7)) * 48
                              + (lane >> 4) * 16);
    #pragma unroll
    for (int nt = 0; nt < 4; nt++)
        boff[nt] = (uint32_t)((wn * 64 + nt * 16 + ((lane >> 4) & 1) * 8 + (lane & 7)) * 48
                              + ((lane >> 3) & 1) * 16) + 6144u;

    float acc[4][8][4];
    #pragma unroll
    for (int mt = 0; mt < 4; mt++)
        #pragma unroll
        for (int nb = 0; nb < 8; nb++)
            #pragma unroll
            for (int e = 0; e < 4; e++) acc[mt][nb][e] = 0.f;

    issue_stage(0, 0);
    issue_stage(1, 1);
    issue_stage(2, 2);

    for (int kk = 0; kk < 32; kk++) {
        asm volatile("cp.async.wait_group 2;" ::: "memory");
        __syncthreads();

        if (kk + 3 < 32) issue_stage(kk + 3, (kk + 3) & 3);
        else asm volatile("cp.async.commit_group;" ::: "memory");

        const uint32_t sa = sbase + (uint32_t)(kk & 3) * HSTAGE;

        uint32_t af[4][4], bfr[4][4];
        #pragma unroll
        for (int mt = 0; mt < 4; mt++)
            ldsm4(af[mt][0], af[mt][1], af[mt][2], af[mt][3], sa + aoff[mt]);
        #pragma unroll
        for (int nt = 0; nt < 4; nt++)
            ldsm4(bfr[nt][0], bfr[nt][1], bfr[nt][2], bfr[nt][3], sa + boff[nt]);

        #pragma unroll
        for (int mt = 0; mt < 4; mt++)
            #pragma unroll
            for (int nt = 0; nt < 4; nt++) {
                mma_f16(acc[mt][2*nt][0], acc[mt][2*nt][1], acc[mt][2*nt][2], acc[mt][2*nt][3],
                        af[mt][0], af[mt][1], af[mt][2], af[mt][3],
                        bfr[nt][0], bfr[nt][1]);
                mma_f16(acc[mt][2*nt+1][0], acc[mt][2*nt+1][1], acc[mt][2*nt+1][2], acc[mt][2*nt+1][3],
                        af[mt][0], af[mt][1], af[mt][2], af[mt][3],
                        bfr[nt][2], bfr[nt][3]);
            }
    }

    const int r  = lane >> 2;
    const int cp = (lane & 3) * 2;
    const int region = col0 >> 9;            // 0=q, 1=k, 2=v

    if (region == 0) {
        #pragma unroll
        for (int mt = 0; mt < 4; mt++) {
            #pragma unroll
            for (int nb = 0; nb < 8; nb++) {
                const int qc = (col0 + wn * 64 + nb * 8 + cp) & 511;
                const long r1 = row0 + wm * 64 + mt * 16 + r;
                *(float2*)(g_q + r1 * 512 + qc)       = make_float2(acc[mt][nb][0], acc[mt][nb][1]);
                *(float2*)(g_q + (r1 + 8) * 512 + qc) = make_float2(acc[mt][nb][2], acc[mt][nb][3]);
            }
        }
    } else {
        // smem-staged transpose: two 64-col halves (owned by warps with wn==half)
        float* ts = (float*)sm;              // 128 x 67 f32
        float2* base_g = (region == 1) ? g_ktp : g_vtp;
        const int b    = row0 >> 12;
        const int tok0 = row0 & 4095;
        const int hbase = (col0 & 511) >> 6; // 0,2,4,6

        #pragma unroll
        for (int hh2 = 0; hh2 < 2; hh2++) {
            __syncthreads();
            if (wn == hh2) {
                #pragma unroll
                for (int mt = 0; mt < 4; mt++) {
                    #pragma unroll
                    for (int nb = 0; nb < 8; nb++) {
                        const int c64 = nb * 8 + cp;
                        const int lr  = wm * 64 + mt * 16 + r;
                        ts[lr * 67 + c64]           = acc[mt][nb][0];
                        ts[lr * 67 + c64 + 1]       = acc[mt][nb][1];
                        ts[(lr + 8) * 67 + c64]     = acc[mt][nb][2];
                        ts[(lr + 8) * 67 + c64 + 1] = acc[mt][nb][3];
                    }
                }
            }
            __syncthreads();
            const int h = hbase + hh2;
            float2* dst = base_g + ((long)(((b << 3) | h) * 32)) * NTOK + tok0 + tid;
            #pragma unroll
            for (int dp = 0; dp < 32; dp++) {
                dst[(long)dp * NTOK] = make_float2(ts[tid * 67 + 2 * dp],
                                                   ts[tid * 67 + 2 * dp + 1]);
            }
        }
    }
}

// ================= GEMM2: output projection, CTA 64x128 (grid 512), bias =================
#define OSTAGE 9216            // A 64x48 (3072) + B 128x48 (6144)
#define OSMEM  (4 * OSTAGE)

__global__ __launch_bounds__(128)
void tgemm_out(const __half* __restrict__ A, const __half* __restrict__ Bt,
               const float* __restrict__ bias, float* __restrict__ C)
{
    extern __shared__ char sm[];
    const uint32_t sbase = smem_u32(sm);

    const int tid  = threadIdx.x;
    const int lane = tid & 31;
    const int wid  = tid >> 5;
    const int wm   = wid >> 1;          // 0..1 -> m offset wm*32
    const int wn   = wid & 1;           // 0..1 -> n offset wn*64

    const int row0 = blockIdx.y * 64;
    const int col0 = blockIdx.x * 128;

    // A loader: 64 rows x 2 chunks -> 128 threads, one cp16 each
    const int a_row = tid >> 1;
    const int a_ch  = tid & 1;
    const __half* Ap = A + (long)(row0 + a_row) * 512 + a_ch * 8;
    const uint32_t dA = (uint32_t)(a_row * 48 + a_ch * 16);
    // B loader: 128 rows, two cp16 each
    const __half* Bp = Bt + (long)(col0 + tid) * 512;
    const uint32_t dB = 3072u + (uint32_t)(tid * 48);

    auto issue_stage = [&](int kk, int s) {
        const uint32_t so = sbase + (uint32_t)s * OSTAGE;
        const long ko = (long)kk * 16;
        cp16(so + dA,      Ap + ko);
        cp16(so + dB,      Bp + ko);
        cp16(so + dB + 16, Bp + ko + 8);
        asm volatile("cp.async.commit_group;" ::: "memory");
    };

    uint32_t aoff[2], boff[4];
    #pragma unroll
    for (int mt = 0; mt < 2; mt++)
        aoff[mt] = (uint32_t)((wm * 32 + mt * 16 + ((lane >> 3) & 1) * 8 + (lane & 7)) * 48
                              + (lane >> 4) * 16);
    #pragma unroll
    for (int nt = 0; nt < 4; nt++)
        boff[nt] = 3072u + (uint32_t)((wn * 64 + nt * 16 + ((lane >> 4) & 1) * 8 + (lane & 7)) * 48
                                      + ((lane >> 3) & 1) * 16);

    float acc[2][8][4];
    #pragma unroll
    for (int mt = 0; mt < 2; mt++)
        #pragma unroll
        for (int nb = 0; nb < 8; nb++)
            #pragma unroll
            for (int e = 0; e < 4; e++) acc[mt][nb][e] = 0.f;

    issue_stage(0, 0);
    issue_stage(1, 1);
    issue_stage(2, 2);

    for (int kk = 0; kk < 32; kk++) {
        asm volatile("cp.async.wait_group 2;" ::: "memory");
        __syncthreads();

        if (kk + 3 < 32) issue_stage(kk + 3, (kk + 3) & 3);
        else asm volatile("cp.async.commit_group;" ::: "memory");

        const uint32_t sa = sbase + (uint32_t)(kk & 3) * OSTAGE;

        uint32_t af[2][4], bfr[4][4];
        #pragma unroll
        for (int mt = 0; mt < 2; mt++)
            ldsm4(af[mt][0], af[mt][1], af[mt][2], af[mt][3], sa + aoff[mt]);
        #pragma unroll
        for (int nt = 0; nt < 4; nt++)
            ldsm4(bfr[nt][0], bfr[nt][1], bfr[nt][2], bfr[nt][3], sa + boff[nt]);

        #pragma unroll
        for (int mt = 0; mt < 2; mt++)
            #pragma unroll
            for (int nt = 0; nt < 4; nt++) {
                mma_f16(acc[mt][2*nt][0], acc[mt][2*nt][1], acc[mt][2*nt][2], acc[mt][2*nt][3],
                        af[mt][0], af[mt][1], af[mt][2], af[mt][3],
                        bfr[nt][0], bfr[nt][1]);
                mma_f16(acc[mt][2*nt+1][0], acc[mt][2*nt+1][1], acc[mt][2*nt+1][2], acc[mt][2*nt+1][3],
                        af[mt][0], af[mt][1], af[mt][2], af[mt][3],
                        bfr[nt][2], bfr[nt][3]);
            }
    }

    const int r  = lane >> 2;
    const int cp = (lane & 3) * 2;
    #pragma unroll
    for (int mt = 0; mt < 2; mt++) {
        #pragma unroll
        for (int nb = 0; nb < 8; nb++) {
            const int cc = col0 + wn * 64 + nb * 8 + cp;
            const float bx = bias[cc], by = bias[cc + 1];
            const long r1 = row0 + wm * 32 + mt * 16 + r;
            *(float2*)(C + r1 * 512 + cc)       = make_float2(acc[mt][nb][0] + bx, acc[mt][nb][1] + by);
            *(float2*)(C + (r1 + 8) * 512 + cc) = make_float2(acc[mt][nb][2] + bx, acc[mt][nb][3] + by);
        }
    }
}

// ---------------- windowed attention: d-split across 4 warps + fused BOS ----------------
__constant__ int C_DF[14] = {-1,-1,-1,-1,-1,-1,-1,-1,-1, 0, 0, 0, 0, 0};
__constant__ int C_DH[14] = {-1,-1,-1, 0, 0, 0, 1, 1, 1,-1,-1,-1, 0, 0};
__constant__ int C_DW[14] = {-1, 0, 1,-1, 0, 1,-1, 0, 1,-1, 0, 1,-1, 0};

__global__ __launch_bounds__(128, 8)
void attn_kernel()
{
    __shared__ float qs[2112];
    __shared__ float ps[4][15][32];

    const int blk  = blockIdx.x;
    const int tid  = threadIdx.x;

    if (blk == 2048) {     // fused BOS rows: zh[b,0,:] = f16(v(token 0))
        for (int e = tid; e < 1024; e += 128) {
            const int b = e >> 9, t = e & 511;
            const int h = t >> 6, d = t & 63;
            const float2 v = g_vtp[((long)(((b << 3) | h) * 32 + (d >> 1))) * NTOK];
            g_zh[(long)b * NTOK * 512 + t] = __float2half((d & 1) ? v.y : v.x);
        }
        return;
    }

    const int w    = tid >> 5;
    const int lane = tid & 31;
    const int grp  = blk & 127;
    const int bh   = blk >> 7;
    const int b    = bh >> 3;
    const int h    = bh & 7;
    const int i0   = grp * 32;
    const int f    = i0 >> 10;
    const int hh   = (i0 >> 5) & 31;
    const int i    = i0 + lane;

    {
        const int r = tid >> 2;
        const int c = (tid & 3) * 16;
        const int tk = min(i0 + r, NPOS - 1) + 1;
        const float* src = g_q + (long)(b * NTOK + tk) * 512 + h * 64 + c;
        #pragma unroll
        for (int j = 0; j < 16; j += 4) {
            float4 v = *(const float4*)(src + j);
            qs[r * 65 + c + j]     = v.x;
            qs[r * 65 + c + j + 1] = v.y;
            qs[r * 65 + c + j + 2] = v.z;
            qs[r * 65 + c + j + 3] = v.w;
        }
    }
    __syncthreads();

    float q[16];
    #pragma unroll
    for (int j = 0; j < 16; j++) q[j] = qs[lane * 65 + w * 16 + j] * SCALE_Q;

    const float2* ktb = g_ktp + ((long)bh * 32 + w * 8) * NTOK;
    const float2* vtb = g_vtp + ((long)bh * 32 + w * 8) * NTOK;

    {   // BOS
        float a0 = 0.f, a1 = 0.f;
        #pragma unroll
        for (int dp = 0; dp < 8; dp++) {
            const float2 kk = ktb[(long)dp * NTOK];
            a0 += q[2 * dp]     * kk.x;
            a1 += q[2 * dp + 1] * kk.y;
        }
        ps[w][0][lane] = a0 + a1;
    }
    #pragma unroll
    for (int s = 0; s < 14; s++) {
        const int df = C_DF[s], dh = C_DH[s], dw = C_DW[s];
        const int off = df * 1024 + dh * 32 + dw;
        const int warp_ok = (f + df >= 0) && ((unsigned)(hh + dh) < 32u);
        float acc = 0.f;
        if (warp_ok) {
            const int t = min(max(i + off, 0), NPOS - 1) + 1;
            const float2* kp = ktb + t;
            float a0 = 0.f, a1 = 0.f;
            #pragma unroll
            for (int dp = 0; dp < 8; dp++) {
                const float2 kk = kp[(long)dp * NTOK];
                a0 += q[2 * dp]     * kk.x;
                a1 += q[2 * dp + 1] * kk.y;
            }
            acc = a0 + a1;
        }
        ps[w][s + 1][lane] = acc;
    }
    __syncthreads();

    const float NEG_INF = __int_as_float(0xff800000);
    float p[15];
    {
        p[0] = ps[0][0][lane] + ps[1][0][lane] + ps[2][0][lane] + ps[3][0][lane];
        #pragma unroll
        for (int s = 0; s < 14; s++) {
            const int df = C_DF[s], dh = C_DH[s], dw = C_DW[s];
            const int ok = (f + df >= 0) && ((unsigned)(hh + dh) < 32u)
                        && ((unsigned)(lane + dw) < 32u) && (i < NPOS);
            p[s + 1] = ok ? (ps[0][s + 1][lane] + ps[1][s + 1][lane]
                           + ps[2][s + 1][lane] + ps[3][s + 1][lane]) : NEG_INF;
        }
        float m = p[0];
        #pragma unroll
        for (int s = 1; s < 15; s++) m = fmaxf(m, p[s]);
        float den = 0.f;
        #pragma unroll
        for (int s = 0; s < 15; s++) { p[s] = __expf(p[s] - m); den += p[s]; }
        const float inv = 1.f / den;
        #pragma unroll
        for (int s = 0; s < 15; s++) p[s] *= inv;
    }

    float o[16];
    #pragma unroll
    for (int d = 0; d < 16; d++) o[d] = 0.f;
    {   // BOS
        const float pw = p[0];
        #pragma unroll
        for (int dp = 0; dp < 8; dp++) {
            const float2 vv = vtb[(long)dp * NTOK];
            o[2 * dp]     += pw * vv.x;
            o[2 * dp + 1] += pw * vv.y;
        }
    }
    #pragma unroll
    for (int s = 0; s < 14; s++) {
        const int df = C_DF[s], dh = C_DH[s], dw = C_DW[s];
        const int warp_ok = (f + df >= 0) && ((unsigned)(hh + dh) < 32u);
        if (warp_ok) {
            const int off = df * 1024 + dh * 32 + dw;
            const int t = min(max(i + off, 0), NPOS - 1) + 1;
            const float pw = p[s + 1];
            const float2* vp = vtb + t;
            #pragma unroll
            for (int dp = 0; dp < 8; dp++) {
                const float2 vv = vp[(long)dp * NTOK];
                o[2 * dp]     += pw * vv.x;
                o[2 * dp + 1] += pw * vv.y;
            }
        }
    }
    __syncthreads();

    #pragma unroll
    for (int d = 0; d < 16; d++) qs[(w * 16 + d) * 33 + lane] = o[d];
    __syncthreads();

    {
        const int r = tid >> 2;
        const int c = (tid & 3) * 16;
        const int irow = i0 + r;
        if (irow < NPOS) {
            __half* dst = g_zh + (long)(b * NTOK + irow + 1) * 512 + h * 64 + c;
            #pragma unroll
            for (int j = 0; j < 16; j += 2) {
                const float x0 = qs[(c + j) * 33 + r];
                const float x1 = qs[(c + j + 1) * 33 + r];
                *(__half2*)(dst + j) = __floats2half2_rn(x0, x1);
            }
        }
    }
}

// ---------------- launch ----------------
extern "C" void kernel_launch(void* const* d_in, const int* in_sizes, int n_in,
                              void* d_out, int out_size)
{
    const float* x   = (const float*)d_in[0];
    const float* Wq  = (const float*)d_in[1];
    const float* Wkv = (const float*)d_in[2];
    const float* Wo  = (const float*)d_in[3];
    const float* bo  = (const float*)d_in[4];
    float* out = (float*)d_out;

    __half *xh, *wqkvt, *wot, *zh;
    cudaGetSymbolAddress((void**)&xh,    g_xh);
    cudaGetSymbolAddress((void**)&zh,    g_zh);
    cudaGetSymbolAddress((void**)&wqkvt, g_wqkvt);
    cudaGetSymbolAddress((void**)&wot,   g_wot);

    cudaFuncSetAttribute(tgemm_qkv, cudaFuncAttributeMaxDynamicSharedMemorySize, HSMEM);
    cudaFuncSetAttribute(tgemm_out, cudaFuncAttributeMaxDynamicSharedMemorySize, OSMEM);

    // 0) fused prologue
    prep_kernel<<<4096 + 256 + 512 + 256, 256>>>(x, Wq, Wkv, Wo);

    // 1) fused QKV projection with coalesced routing epilogue
    tgemm_qkv<<<dim3(QKVN / 128, MROWS / 128), 128, HSMEM>>>(xh, wqkvt);

    // 2) windowed causal attention + fused BOS rows
    attn_kernel<<<2049, 128>>>();

    // 3) output projection + bias (64x128 tiles, grid 512)
    tgemm_out<<<dim3(512 / 128, MROWS / 64), 128, OSMEM>>>(zh, wot, bo, out);
}

// round 14
// speedup vs baseline: 1.4443x; 1.0050x over previous
#include <cuda_runtime.h>
#include <cuda_fp16.h>
#include <cstdint>

// ---------------- problem constants ----------------
#define NTOK      4096
#define BATCH     2
#define MROWS     8192
#define NPOS      4095
#define SCALE_Q   0.125f
#define QKVN      1536

// ---------------- scratch ----------------
__device__ __half g_xh   [MROWS * 512];
__device__ float  g_q    [MROWS * 512];
__device__ __half g_zh   [MROWS * 512];
__device__ __half g_wqkvt[QKVN * 512];
__device__ __half g_wot  [512 * 512];
__device__ float2 g_ktp  [16 * 32 * NTOK];
__device__ float2 g_vtp  [16 * 32 * NTOK];

// ---------------- helpers ----------------
__device__ __forceinline__ uint32_t smem_u32(const void* p) {
    uint32_t a;
    asm("{ .reg .u64 t; cvta.to.shared.u64 t, %1; cvt.u32.u64 %0, t; }" : "=r"(a) : "l"(p));
    return a;
}
__device__ __forceinline__ void cp16(uint32_t dst, const void* src) {
    asm volatile("cp.async.cg.shared.global [%0], [%1], 16;" :: "r"(dst), "l"(src));
}
__device__ __forceinline__ void ldsm4(uint32_t& r0, uint32_t& r1, uint32_t& r2, uint32_t& r3, uint32_t a) {
    asm volatile("ldmatrix.sync.aligned.m8n8.x4.shared.b16 {%0,%1,%2,%3}, [%4];"
                 : "=r"(r0), "=r"(r1), "=r"(r2), "=r"(r3) : "r"(a));
}
__device__ __forceinline__ void mma_f16(float& d0, float& d1, float& d2, float& d3,
                                        uint32_t a0, uint32_t a1, uint32_t a2, uint32_t a3,
                                        uint32_t b0, uint32_t b1) {
    asm volatile(
        "mma.sync.aligned.m16n8k16.row.col.f32.f16.f16.f32 "
        "{%0,%1,%2,%3}, {%4,%5,%6,%7}, {%8,%9}, {%0,%1,%2,%3};"
        : "+f"(d0), "+f"(d1), "+f"(d2), "+f"(d3)
        : "r"(a0), "r"(a1), "r"(a2), "r"(a3), "r"(b0), "r"(b1));
}

// ---------------- fused prologue ----------------
__device__ __forceinline__ void do_transpose(const float* __restrict__ in, __half* __restrict__ out,
                                             int R, int C, int bx, int by, int tx, int ty,
                                             float (*t)[33])
{
    const int x0 = bx * 32, y0 = by * 32;
    #pragma unroll
    for (int j = 0; j < 32; j += 8)
        t[ty + j][tx] = in[(long)(y0 + ty + j) * C + x0 + tx];
    __syncthreads();
    #pragma unroll
    for (int j = 0; j < 32; j += 8)
        out[(long)(x0 + ty + j) * R + y0 + tx] = __float2half(t[tx][ty + j]);
}

__global__ __launch_bounds__(256)
void prep_kernel(const float* __restrict__ x, const float* __restrict__ Wq,
                 const float* __restrict__ Wkv, const float* __restrict__ Wo)
{
    __shared__ float t[32][33];
    const int blk = blockIdx.x;
    const int tid = threadIdx.x;
    if (blk < 4096) {
        const long i = ((long)blk * 256 + tid) * 4;
        float4 v = *(const float4*)(x + i);
        *(__half2*)(g_xh + i)     = __floats2half2_rn(v.x, v.y);
        *(__half2*)(g_xh + i + 2) = __floats2half2_rn(v.z, v.w);
        return;
    }
    const int tx = tid & 31, ty = tid >> 5;
    if (blk < 4096 + 256) {
        const int z = blk - 4096;
        do_transpose(Wq, g_wqkvt, 512, 512, z & 15, z >> 4, tx, ty, t);
    } else if (blk < 4096 + 256 + 512) {
        const int z = blk - 4096 - 256;
        do_transpose(Wkv, g_wqkvt + 512 * 512, 512, 1024, z & 31, z >> 5, tx, ty, t);
    } else {
        const int z = blk - 4096 - 256 - 512;
        do_transpose(Wo, g_wot, 512, 512, z & 15, z >> 4, tx, ty, t);
    }
}

// ================= GEMM1: QKV projection, CTA 128x128, routing epilogue =================
#define HSTAGE 12288
#define HSMEM  (4 * HSTAGE)

__global__ __launch_bounds__(128)
void tgemm_qkv(const __half* __restrict__ A, const __half* __restrict__ Bt)
{
    extern __shared__ char sm[];
    const uint32_t sbase = smem_u32(sm);

    const int tid  = threadIdx.x;
    const int lane = tid & 31;
    const int wid  = tid >> 5;
    const int wm   = wid >> 1;
    const int wn   = wid & 1;

    const int row0 = blockIdx.y * 128;
    const int col0 = blockIdx.x * 128;

    const __half* Ap = A  + (long)(row0 + tid) * 512;
    const __half* Bp = Bt + (long)(col0 + tid) * 512;
    const uint32_t dRow = (uint32_t)(tid * 48);

    auto issue_stage = [&](int kk, int s) {
        const uint32_t so = sbase + (uint32_t)s * HSTAGE;
        const long ko = (long)kk * 16;
        cp16(so + dRow,              Ap + ko);
        cp16(so + dRow + 16,         Ap + ko + 8);
        cp16(so + 6144u + dRow,      Bp + ko);
        cp16(so + 6144u + dRow + 16, Bp + ko + 8);
        asm volatile("cp.async.commit_group;" ::: "memory");
    };

    uint32_t aoff[4], boff[4];
    #pragma unroll
    for (int mt = 0; mt < 4; mt++)
        aoff[mt] = (uint32_t)((wm * 64 + mt * 16 + ((lane >> 3) & 1) * 8 + (lane & 7)) * 48
                              + (lane >> 4) * 16);
    #pragma unroll
    for (int nt = 0; nt < 4; nt++)
        boff[nt] = (uint32_t)((wn * 64 + nt * 16 + ((lane >> 4) & 1) * 8 + (lane & 7)) * 48
                              + ((lane >> 3) & 1) * 16) + 6144u;

    float acc[4][8][4];
    #pragma unroll
    for (int mt = 0; mt < 4; mt++)
        #pragma unroll
        for (int nb = 0; nb < 8; nb++)
            #pragma unroll
            for (int e = 0; e < 4; e++) acc[mt][nb][e] = 0.f;

    issue_stage(0, 0);
    issue_stage(1, 1);
    issue_stage(2, 2);

    for (int kk = 0; kk < 32; kk++) {
        asm volatile("cp.async.wait_group 2;" ::: "memory");
        __syncthreads();

        if (kk + 3 < 32) issue_stage(kk + 3, (kk + 3) & 3);
        else asm volatile("cp.async.commit_group;" ::: "memory");

        const uint32_t sa = sbase + (uint32_t)(kk & 3) * HSTAGE;

        uint32_t af[4][4], bfr[4][4];
        #pragma unroll
        for (int mt = 0; mt < 4; mt++)
            ldsm4(af[mt][0], af[mt][1], af[mt][2], af[mt][3], sa + aoff[mt]);
        #pragma unroll
        for (int nt = 0; nt < 4; nt++)
            ldsm4(bfr[nt][0], bfr[nt][1], bfr[nt][2], bfr[nt][3], sa + boff[nt]);

        #pragma unroll
        for (int mt = 0; mt < 4; mt++)
            #pragma unroll
            for (int nt = 0; nt < 4; nt++) {
                mma_f16(acc[mt][2*nt][0], acc[mt][2*nt][1], acc[mt][2*nt][2], acc[mt][2*nt][3],
                        af[mt][0], af[mt][1], af[mt][2], af[mt][3],
                        bfr[nt][0], bfr[nt][1]);
                mma_f16(acc[mt][2*nt+1][0], acc[mt][2*nt+1][1], acc[mt][2*nt+1][2], acc[mt][2*nt+1][3],
                        af[mt][0], af[mt][1], af[mt][2], af[mt][3],
                        bfr[nt][2], bfr[nt][3]);
            }
    }

    const int r  = lane >> 2;
    const int cp = (lane & 3) * 2;
    const int region = col0 >> 9;            // 0=q, 1=k, 2=v

    if (region == 0) {
        #pragma unroll
        for (int mt = 0; mt < 4; mt++) {
            #pragma unroll
            for (int nb = 0; nb < 8; nb++) {
                const int qc = (col0 + wn * 64 + nb * 8 + cp) & 511;
                const long r1 = row0 + wm * 64 + mt * 16 + r;
                *(float2*)(g_q + r1 * 512 + qc)       = make_float2(acc[mt][nb][0], acc[mt][nb][1]);
                *(float2*)(g_q + (r1 + 8) * 512 + qc) = make_float2(acc[mt][nb][2], acc[mt][nb][3]);
            }
        }
    } else {
        float* ts = (float*)sm;              // 128 x 67 f32
        float2* base_g = (region == 1) ? g_ktp : g_vtp;
        const int b    = row0 >> 12;
        const int tok0 = row0 & 4095;
        const int hbase = (col0 & 511) >> 6;

        #pragma unroll
        for (int hh2 = 0; hh2 < 2; hh2++) {
            __syncthreads();
            if (wn == hh2) {
                #pragma unroll
                for (int mt = 0; mt < 4; mt++) {
                    #pragma unroll
                    for (int nb = 0; nb < 8; nb++) {
                        const int c64 = nb * 8 + cp;
                        const int lr  = wm * 64 + mt * 16 + r;
                        ts[lr * 67 + c64]           = acc[mt][nb][0];
                        ts[lr * 67 + c64 + 1]       = acc[mt][nb][1];
                        ts[(lr + 8) * 67 + c64]     = acc[mt][nb][2];
                        ts[(lr + 8) * 67 + c64 + 1] = acc[mt][nb][3];
                    }
                }
            }
            __syncthreads();
            const int h = hbase + hh2;
            float2* dst = base_g + ((long)(((b << 3) | h) * 32)) * NTOK + tok0 + tid;
            #pragma unroll
            for (int dp = 0; dp < 32; dp++) {
                dst[(long)dp * NTOK] = make_float2(ts[tid * 67 + 2 * dp],
                                                   ts[tid * 67 + 2 * dp + 1]);
            }
        }
    }
}

// ================= GEMM2: output projection, CTA 64x64 (grid 1024), bias =================
#define OSTAGE 6144            // A 64x48 (3072) + B 64x48 (3072)
#define OSMEM  (4 * OSTAGE)

__global__ __launch_bounds__(128)
void tgemm_out(const __half* __restrict__ A, const __half* __restrict__ Bt,
               const float* __restrict__ bias, float* __restrict__ C)
{
    extern __shared__ char sm[];
    const uint32_t sbase = smem_u32(sm);

    const int tid  = threadIdx.x;
    const int lane = tid & 31;
    const int wid  = tid >> 5;
    const int wm   = wid >> 1;          // 0..1 -> m offset wm*32
    const int wn   = wid & 1;           // 0..1 -> n offset wn*32

    const int row0 = blockIdx.y * 64;
    const int col0 = blockIdx.x * 64;

    const int l_row = tid >> 1;
    const int l_ch  = tid & 1;
    const __half* Ap = A  + (long)(row0 + l_row) * 512 + l_ch * 8;
    const __half* Bp = Bt + (long)(col0 + l_row) * 512 + l_ch * 8;
    const uint32_t dA = (uint32_t)(l_row * 48 + l_ch * 16);
    const uint32_t dB = 3072u + dA;

    auto issue_stage = [&](int kk, int s) {
        const uint32_t so = sbase + (uint32_t)s * OSTAGE;
        const long ko = (long)kk * 16;
        cp16(so + dA, Ap + ko);
        cp16(so + dB, Bp + ko);
        asm volatile("cp.async.commit_group;" ::: "memory");
    };

    uint32_t aoff[2], boff[2];
    #pragma unroll
    for (int mt = 0; mt < 2; mt++)
        aoff[mt] = (uint32_t)((wm * 32 + mt * 16 + ((lane >> 3) & 1) * 8 + (lane & 7)) * 48
                              + (lane >> 4) * 16);
    #pragma unroll
    for (int nt = 0; nt < 2; nt++)
        boff[nt] = 3072u + (uint32_t)((wn * 32 + nt * 16 + ((lane >> 4) & 1) * 8 + (lane & 7)) * 48
                                      + ((lane >> 3) & 1) * 16);

    float acc[2][4][4];
    #pragma unroll
    for (int mt = 0; mt < 2; mt++)
        #pragma unroll
        for (int nb = 0; nb < 4; nb++)
            #pragma unroll
            for (int e = 0; e < 4; e++) acc[mt][nb][e] = 0.f;

    issue_stage(0, 0);
    issue_stage(1, 1);
    issue_stage(2, 2);

    for (int kk = 0; kk < 32; kk++) {
        asm volatile("cp.async.wait_group 2;" ::: "memory");
        __syncthreads();

        if (kk + 3 < 32) issue_stage(kk + 3, (kk + 3) & 3);
        else asm volatile("cp.async.commit_group;" ::: "memory");

        const uint32_t sa = sbase + (uint32_t)(kk & 3) * OSTAGE;

        uint32_t af[2][4], bfr[2][4];
        #pragma unroll
        for (int mt = 0; mt < 2; mt++)
            ldsm4(af[mt][0], af[mt][1], af[mt][2], af[mt][3], sa + aoff[mt]);
        #pragma unroll
        for (int nt = 0; nt < 2; nt++)
            ldsm4(bfr[nt][0], bfr[nt][1], bfr[nt][2], bfr[nt][3], sa + boff[nt]);

        #pragma unroll
        for (int mt = 0; mt < 2; mt++)
            #pragma unroll
            for (int nt = 0; nt < 2; nt++) {
                mma_f16(acc[mt][2*nt][0], acc[mt][2*nt][1], acc[mt][2*nt][2], acc[mt][2*nt][3],
                        af[mt][0], af[mt][1], af[mt][2], af[mt][3],
                        bfr[nt][0], bfr[nt][1]);
                mma_f16(acc[mt][2*nt+1][0], acc[mt][2*nt+1][1], acc[mt][2*nt+1][2], acc[mt][2*nt+1][3],
                        af[mt][0], af[mt][1], af[mt][2], af[mt][3],
                        bfr[nt][2], bfr[nt][3]);
            }
    }

    const int r  = lane >> 2;
    const int cp = (lane & 3) * 2;
    #pragma unroll
    for (int mt = 0; mt < 2; mt++) {
        #pragma unroll
        for (int nb = 0; nb < 4; nb++) {
            const int cc = col0 + wn * 32 + nb * 8 + cp;
            const float bx = bias[cc], by = bias[cc + 1];
            const long r1 = row0 + wm * 32 + mt * 16 + r;
            *(float2*)(C + r1 * 512 + cc)       = make_float2(acc[mt][nb][0] + bx, acc[mt][nb][1] + by);
            *(float2*)(C + (r1 + 8) * 512 + cc) = make_float2(acc[mt][nb][2] + bx, acc[mt][nb][3] + by);
        }
    }
}

// ---------------- windowed attention: 8-way d-split, 256 threads ----------------
__constant__ int C_DF[14] = {-1,-1,-1,-1,-1,-1,-1,-1,-1, 0, 0, 0, 0, 0};
__constant__ int C_DH[14] = {-1,-1,-1, 0, 0, 0, 1, 1, 1,-1,-1,-1, 0, 0};
__constant__ int C_DW[14] = {-1, 0, 1,-1, 0, 1,-1, 0, 1,-1, 0, 1,-1, 0};

__global__ __launch_bounds__(256, 4)
void attn_kernel()
{
    __shared__ float qs[2112];           // 32x65 staging / 64x33 output
    __shared__ float ps[8][15][32];      // per-warp partial sims

    const int blk  = blockIdx.x;
    const int tid  = threadIdx.x;

    if (blk == 2048) {     // fused BOS rows
        for (int e = tid; e < 1024; e += 256) {
            const int b = e >> 9, t = e & 511;
            const int h = t >> 6, d = t & 63;
            const float2 v = g_vtp[((long)(((b << 3) | h) * 32 + (d >> 1))) * NTOK];
            g_zh[(long)b * NTOK * 512 + t] = __float2half((d & 1) ? v.y : v.x);
        }
        return;
    }

    const int w    = tid >> 5;           // 0..7, owns d [8w, 8w+8)
    const int lane = tid & 31;
    const int grp  = blk & 127;
    const int bh   = blk >> 7;
    const int b    = bh >> 3;
    const int h    = bh & 7;
    const int i0   = grp * 32;
    const int f    = i0 >> 10;
    const int hh   = (i0 >> 5) & 31;
    const int i    = i0 + lane;

    // ---- stage q (coalesced): thread -> (row tid>>3, 8 cols) ----
    {
        const int r = tid >> 3;
        const int c = (tid & 7) * 8;
        const int tk = min(i0 + r, NPOS - 1) + 1;
        const float* src = g_q + (long)(b * NTOK + tk) * 512 + h * 64 + c;
        float4 v0 = *(const float4*)(src);
        float4 v1 = *(const float4*)(src + 4);
        qs[r * 65 + c + 0] = v0.x; qs[r * 65 + c + 1] = v0.y;
        qs[r * 65 + c + 2] = v0.z; qs[r * 65 + c + 3] = v0.w;
        qs[r * 65 + c + 4] = v1.x; qs[r * 65 + c + 5] = v1.y;
        qs[r * 65 + c + 6] = v1.z; qs[r * 65 + c + 7] = v1.w;
    }
    __syncthreads();

    float q[8];
    #pragma unroll
    for (int j = 0; j < 8; j++) q[j] = qs[lane * 65 + w * 8 + j] * SCALE_Q;

    const float2* ktb = g_ktp + ((long)bh * 32 + w * 4) * NTOK;
    const float2* vtb = g_vtp + ((long)bh * 32 + w * 4) * NTOK;

    // ---- partial sims ----
    {   // BOS
        float a0 = 0.f, a1 = 0.f;
        #pragma unroll
        for (int dp = 0; dp < 4; dp++) {
            const float2 kk = ktb[(long)dp * NTOK];
            a0 += q[2 * dp]     * kk.x;
            a1 += q[2 * dp + 1] * kk.y;
        }
        ps[w][0][lane] = a0 + a1;
    }
    #pragma unroll
    for (int s = 0; s < 14; s++) {
        const int df = C_DF[s], dh = C_DH[s], dw = C_DW[s];
        const int off = df * 1024 + dh * 32 + dw;
        const int warp_ok = (f + df >= 0) && ((unsigned)(hh + dh) < 32u);
        float acc = 0.f;
        if (warp_ok) {
            const int t = min(max(i + off, 0), NPOS - 1) + 1;
            const float2* kp = ktb + t;
            float a0 = 0.f, a1 = 0.f;
            #pragma unroll
            for (int dp = 0; dp < 4; dp++) {
                const float2 kk = kp[(long)dp * NTOK];
                a0 += q[2 * dp]     * kk.x;
                a1 += q[2 * dp + 1] * kk.y;
            }
            acc = a0 + a1;
        }
        ps[w][s + 1][lane] = acc;
    }
    __syncthreads();

    // ---- combine + softmax (each warp redundantly) ----
    const float NEG_INF = __int_as_float(0xff800000);
    float p[15];
    {
        #pragma unroll
        for (int s = 0; s < 15; s++) {
            float v = ps[0][s][lane];
            #pragma unroll
            for (int ww = 1; ww < 8; ww++) v += ps[ww][s][lane];
            p[s] = v;
        }
        #pragma unroll
        for (int s = 0; s < 14; s++) {
            const int df = C_DF[s], dh = C_DH[s], dw = C_DW[s];
            const int ok = (f + df >= 0) && ((unsigned)(hh + dh) < 32u)
                        && ((unsigned)(lane + dw) < 32u) && (i < NPOS);
            if (!ok) p[s + 1] = NEG_INF;
        }
        float m = p[0];
        #pragma unroll
        for (int s = 1; s < 15; s++) m = fmaxf(m, p[s]);
        float den = 0.f;
        #pragma unroll
        for (int s = 0; s < 15; s++) { p[s] = __expf(p[s] - m); den += p[s]; }
        const float inv = 1.f / den;
        #pragma unroll
        for (int s = 0; s < 15; s++) p[s] *= inv;
    }

    // ---- PV: warp computes its 8-d slice ----
    float o[8];
    #pragma unroll
    for (int d = 0; d < 8; d++) o[d] = 0.f;
    {   // BOS
        const float pw = p[0];
        #pragma unroll
        for (int dp = 0; dp < 4; dp++) {
            const float2 vv = vtb[(long)dp * NTOK];
            o[2 * dp]     += pw * vv.x;
            o[2 * dp + 1] += pw * vv.y;
        }
    }
    #pragma unroll
    for (int s = 0; s < 14; s++) {
        const int df = C_DF[s], dh = C_DH[s], dw = C_DW[s];
        const int warp_ok = (f + df >= 0) && ((unsigned)(hh + dh) < 32u);
        if (warp_ok) {
            const int off = df * 1024 + dh * 32 + dw;
            const int t = min(max(i + off, 0), NPOS - 1) + 1;
            const float pw = p[s + 1];
            const float2* vp = vtb + t;
            #pragma unroll
            for (int dp = 0; dp < 4; dp++) {
                const float2 vv = vp[(long)dp * NTOK];
                o[2 * dp]     += pw * vv.x;
                o[2 * dp + 1] += pw * vv.y;
            }
        }
    }
    __syncthreads();   // qs reads done -> reuse as output staging

    #pragma unroll
    for (int d = 0; d < 8; d++) qs[(w * 8 + d) * 33 + lane] = o[d];
    __syncthreads();

    // ---- coalesced f16 store: thread -> (row tid>>3, 8 cols) ----
    {
        const int r = tid >> 3;
        const int c = (tid & 7) * 8;
        const int irow = i0 + r;
        if (irow < NPOS) {
            __half* dst = g_zh + (long)(b * NTOK + irow + 1) * 512 + h * 64 + c;
            #pragma unroll
            for (int j = 0; j < 8; j += 2) {
                const float x0 = qs[(c + j) * 33 + r];
                const float x1 = qs[(c + j + 1) * 33 + r];
                *(__half2*)(dst + j) = __floats2half2_rn(x0, x1);
            }
        }
    }
}

// ---------------- launch ----------------
extern "C" void kernel_launch(void* const* d_in, const int* in_sizes, int n_in,
                              void* d_out, int out_size)
{
    const float* x   = (const float*)d_in[0];
    const float* Wq  = (const float*)d_in[1];
    const float* Wkv = (const float*)d_in[2];
    const float* Wo  = (const float*)d_in[3];
    const float* bo  = (const float*)d_in[4];
    float* out = (float*)d_out;

    __half *xh, *wqkvt, *wot, *zh;
    cudaGetSymbolAddress((void**)&xh,    g_xh);
    cudaGetSymbolAddress((void**)&zh,    g_zh);
    cudaGetSymbolAddress((void**)&wqkvt, g_wqkvt);
    cudaGetSymbolAddress((void**)&wot,   g_wot);

    cudaFuncSetAttribute(tgemm_qkv, cudaFuncAttributeMaxDynamicSharedMemorySize, HSMEM);
    cudaFuncSetAttribute(tgemm_out, cudaFuncAttributeMaxDynamicSharedMemorySize, OSMEM);

    // 0) fused prologue
    prep_kernel<<<4096 + 256 + 512 + 256, 256>>>(x, Wq, Wkv, Wo);

    // 1) fused QKV projection with coalesced routing epilogue
    tgemm_qkv<<<dim3(QKVN / 128, MROWS / 128), 128, HSMEM>>>(xh, wqkvt);

    // 2) windowed causal attention + fused BOS rows (8-way d-split)
    attn_kernel<<<2049, 256>>>();

    // 3) output projection + bias (64x64 tiles, grid 1024)
    tgemm_out<<<dim3(512 / 64, MROWS / 64), 128, OSMEM>>>(zh, wot, bo, out);
}

// round 17
// speedup vs baseline: 1.4531x; 1.0061x over previous
#include <cuda_runtime.h>
#include <cuda_fp16.h>
#include <cstdint>

// ---------------- problem constants ----------------
#define NTOK      4096
#define BATCH     2
#define MROWS     8192
#define NPOS      4095
#define SCALE_Q   0.125f
#define QKVN      1536

// ---------------- scratch ----------------
__device__ __half g_xh   [MROWS * 512];
__device__ float  g_q    [MROWS * 512];
__device__ __half g_zh   [MROWS * 512];
__device__ __half g_wqkvt[QKVN * 512];
__device__ __half g_wot  [512 * 512];
__device__ float2 g_ktp  [16 * 32 * NTOK];
__device__ float2 g_vtp  [16 * 32 * NTOK];

// ---------------- helpers ----------------
__device__ __forceinline__ uint32_t smem_u32(const void* p) {
    uint32_t a;
    asm("{ .reg .u64 t; cvta.to.shared.u64 t, %1; cvt.u32.u64 %0, t; }" : "=r"(a) : "l"(p));
    return a;
}
__device__ __forceinline__ void cp16(uint32_t dst, const void* src) {
    asm volatile("cp.async.cg.shared.global [%0], [%1], 16;" :: "r"(dst), "l"(src));
}
__device__ __forceinline__ void ldsm4(uint32_t& r0, uint32_t& r1, uint32_t& r2, uint32_t& r3, uint32_t a) {
    asm volatile("ldmatrix.sync.aligned.m8n8.x4.shared.b16 {%0,%1,%2,%3}, [%4];"
                 : "=r"(r0), "=r"(r1), "=r"(r2), "=r"(r3) : "r"(a));
}
__device__ __forceinline__ void mma_f16(float& d0, float& d1, float& d2, float& d3,
                                        uint32_t a0, uint32_t a1, uint32_t a2, uint32_t a3,
                                        uint32_t b0, uint32_t b1) {
    asm volatile(
        "mma.sync.aligned.m16n8k16.row.col.f32.f16.f16.f32 "
        "{%0,%1,%2,%3}, {%4,%5,%6,%7}, {%8,%9}, {%0,%1,%2,%3};"
        : "+f"(d0), "+f"(d1), "+f"(d2), "+f"(d3)
        : "r"(a0), "r"(a1), "r"(a2), "r"(a3), "r"(b0), "r"(b1));
}

// ---------------- fused prologue ----------------
__device__ __forceinline__ void do_transpose(const float* __restrict__ in, __half* __restrict__ out,
                                             int R, int C, int bx, int by, int tx, int ty,
                                             float (*t)[33])
{
    const int x0 = bx * 32, y0 = by * 32;
    #pragma unroll
    for (int j = 0; j < 32; j += 8)
        t[ty + j][tx] = in[(long)(y0 + ty + j) * C + x0 + tx];
    __syncthreads();
    #pragma unroll
    for (int j = 0; j < 32; j += 8)
        out[(long)(x0 + ty + j) * R + y0 + tx] = __float2half(t[tx][ty + j]);
}

__global__ __launch_bounds__(256)
void prep_kernel(const float* __restrict__ x, const float* __restrict__ Wq,
                 const float* __restrict__ Wkv, const float* __restrict__ Wo)
{
    __shared__ float t[32][33];
    const int blk = blockIdx.x;
    const int tid = threadIdx.x;
    if (blk < 4096) {
        const long i = ((long)blk * 256 + tid) * 4;
        float4 v = *(const float4*)(x + i);
        *(__half2*)(g_xh + i)     = __floats2half2_rn(v.x, v.y);
        *(__half2*)(g_xh + i + 2) = __floats2half2_rn(v.z, v.w);
        return;
    }
    const int tx = tid & 31, ty = tid >> 5;
    if (blk < 4096 + 256) {
        const int z = blk - 4096;
        do_transpose(Wq, g_wqkvt, 512, 512, z & 15, z >> 4, tx, ty, t);
    } else if (blk < 4096 + 256 + 512) {
        const int z = blk - 4096 - 256;
        do_transpose(Wkv, g_wqkvt + 512 * 512, 512, 1024, z & 31, z >> 5, tx, ty, t);
    } else {
        const int z = blk - 4096 - 256 - 512;
        do_transpose(Wo, g_wot, 512, 512, z & 15, z >> 4, tx, ty, t);
    }
}

// ================= GEMM1: QKV projection, CTA 128x128, k-chunk 32, 3 stages =================
// smem row stride 80B (64B data + 16B pad). Stage: A 128x80 + B 128x80 = 20480B.
#define HSTAGE 20480
#define HSMEM  (3 * HSTAGE)

__global__ __launch_bounds__(128)
void tgemm_qkv(const __half* __restrict__ A, const __half* __restrict__ Bt)
{
    extern __shared__ char sm[];
    const uint32_t sbase = smem_u32(sm);

    const int tid  = threadIdx.x;
    const int lane = tid & 31;
    const int wid  = tid >> 5;
    const int wm   = wid >> 1;
    const int wn   = wid & 1;

    const int row0 = blockIdx.y * 128;
    const int col0 = blockIdx.x * 128;

    const __half* Ap = A  + (long)(row0 + tid) * 512;
    const __half* Bp = Bt + (long)(col0 + tid) * 512;
    const uint32_t dRow = (uint32_t)(tid * 80);

    auto issue_stage = [&](int kk, int s) {
        const uint32_t so = sbase + (uint32_t)s * HSTAGE;
        const long ko = (long)kk * 32;
        #pragma unroll
        for (int c = 0; c < 4; c++) {
            cp16(so + dRow + c * 16,          Ap + ko + c * 8);
            cp16(so + 10240u + dRow + c * 16, Bp + ko + c * 8);
        }
        asm volatile("cp.async.commit_group;" ::: "memory");
    };

    uint32_t aoff[4], boff[4];
    #pragma unroll
    for (int mt = 0; mt < 4; mt++)
        aoff[mt] = (uint32_t)((wm * 64 + mt * 16 + ((lane >> 3) & 1) * 8 + (lane & 7)) * 80
                              + (lane >> 4) * 16);
    #pragma unroll
    for (int nt = 0; nt < 4; nt++)
        boff[nt] = (uint32_t)((wn * 64 + nt * 16 + ((lane >> 4) & 1) * 8 + (lane & 7)) * 80
                              + ((lane >> 3) & 1) * 16) + 10240u;

    float acc[4][8][4];
    #pragma unroll
    for (int mt = 0; mt < 4; mt++)
        #pragma unroll
        for (int nb = 0; nb < 8; nb++)
            #pragma unroll
            for (int e = 0; e < 4; e++) acc[mt][nb][e] = 0.f;

    issue_stage(0, 0);
    issue_stage(1, 1);

    for (int kk = 0; kk < 16; kk++) {
        if (kk < 15) asm volatile("cp.async.wait_group 1;" ::: "memory");
        else         asm volatile("cp.async.wait_group 0;" ::: "memory");
        __syncthreads();

        if (kk + 2 < 16) issue_stage(kk + 2, (kk + 2) % 3);

        const uint32_t sa = sbase + (uint32_t)(kk % 3) * HSTAGE;

        #pragma unroll
        for (int ks = 0; ks < 2; ks++) {
            const uint32_t kso = (uint32_t)(ks * 32);
            uint32_t af[4][4], bfr[4][4];
            #pragma unroll
            for (int mt = 0; mt < 4; mt++)
                ldsm4(af[mt][0], af[mt][1], af[mt][2], af[mt][3], sa + aoff[mt] + kso);
            #pragma unroll
            for (int nt = 0; nt < 4; nt++)
                ldsm4(bfr[nt][0], bfr[nt][1], bfr[nt][2], bfr[nt][3], sa + boff[nt] + kso);

            #pragma unroll
            for (int mt = 0; mt < 4; mt++)
                #pragma unroll
                for (int nt = 0; nt < 4; nt++) {
                    mma_f16(acc[mt][2*nt][0], acc[mt][2*nt][1], acc[mt][2*nt][2], acc[mt][2*nt][3],
                            af[mt][0], af[mt][1], af[mt][2], af[mt][3],
                            bfr[nt][0], bfr[nt][1]);
                    mma_f16(acc[mt][2*nt+1][0], acc[mt][2*nt+1][1], acc[mt][2*nt+1][2], acc[mt][2*nt+1][3],
                            af[mt][0], af[mt][1], af[mt][2], af[mt][3],
                            bfr[nt][2], bfr[nt][3]);
                }
        }
    }

    const int r  = lane >> 2;
    const int cp = (lane & 3) * 2;
    const int region = col0 >> 9;            // 0=q, 1=k, 2=v

    if (region == 0) {
        #pragma unroll
        for (int mt = 0; mt < 4; mt++) {
            #pragma unroll
            for (int nb = 0; nb < 8; nb++) {
                const int qc = (col0 + wn * 64 + nb * 8 + cp) & 511;
                const long r1 = row0 + wm * 64 + mt * 16 + r;
                *(float2*)(g_q + r1 * 512 + qc)       = make_float2(acc[mt][nb][0], acc[mt][nb][1]);
                *(float2*)(g_q + (r1 + 8) * 512 + qc) = make_float2(acc[mt][nb][2], acc[mt][nb][3]);
            }
        }
    } else {
        float* ts = (float*)sm;              // 128 x 67 f32 (34304B < HSMEM)
        float2* base_g = (region == 1) ? g_ktp : g_vtp;
        const int b    = row0 >> 12;
        const int tok0 = row0 & 4095;
        const int hbase = (col0 & 511) >> 6;

        #pragma unroll
        for (int hh2 = 0; hh2 < 2; hh2++) {
            __syncthreads();
            if (wn == hh2) {
                #pragma unroll
                for (int mt = 0; mt < 4; mt++) {
                    #pragma unroll
                    for (int nb = 0; nb < 8; nb++) {
                        const int c64 = nb * 8 + cp;
                        const int lr  = wm * 64 + mt * 16 + r;
                        ts[lr * 67 + c64]           = acc[mt][nb][0];
                        ts[lr * 67 + c64 + 1]       = acc[mt][nb][1];
                        ts[(lr + 8) * 67 + c64]     = acc[mt][nb][2];
                        ts[(lr + 8) * 67 + c64 + 1] = acc[mt][nb][3];
                    }
                }
            }
            __syncthreads();
            const int h = hbase + hh2;
            float2* dst = base_g + ((long)(((b << 3) | h) * 32)) * NTOK + tok0 + tid;
            #pragma unroll
            for (int dp = 0; dp < 32; dp++) {
                dst[(long)dp * NTOK] = make_float2(ts[tid * 67 + 2 * dp],
                                                   ts[tid * 67 + 2 * dp + 1]);
            }
        }
    }
}

// ================= GEMM2: output projection, CTA 64x64, k-chunk 32, 3 stages =================
#define OSTAGE 10240           // A 64x80 (5120) + B 64x80 (5120)
#define OSMEM  (3 * OSTAGE)

__global__ __launch_bounds__(128)
void tgemm_out(const __half* __restrict__ A, const __half* __restrict__ Bt,
               const float* __restrict__ bias, float* __restrict__ C)
{
    extern __shared__ char sm[];
    const uint32_t sbase = smem_u32(sm);

    const int tid  = threadIdx.x;
    const int lane = tid & 31;
    const int wid  = tid >> 5;
    const int wm   = wid >> 1;          // 0..1 -> m offset wm*32
    const int wn   = wid & 1;           // 0..1 -> n offset wn*32

    const int row0 = blockIdx.y * 64;
    const int col0 = blockIdx.x * 64;

    const int l_row = tid >> 1;
    const int l_h   = tid & 1;           // which 32B half of the 64B row
    const __half* Ap = A  + (long)(row0 + l_row) * 512 + l_h * 16;
    const __half* Bp = Bt + (long)(col0 + l_row) * 512 + l_h * 16;
    const uint32_t dA = (uint32_t)(l_row * 80 + l_h * 32);
    const uint32_t dB = 5120u + dA;

    auto issue_stage = [&](int kk, int s) {
        const uint32_t so = sbase + (uint32_t)s * OSTAGE;
        const long ko = (long)kk * 32;
        cp16(so + dA,      Ap + ko);
        cp16(so + dA + 16, Ap + ko + 8);
        cp16(so + dB,      Bp + ko);
        cp16(so + dB + 16, Bp + ko + 8);
        asm volatile("cp.async.commit_group;" ::: "memory");
    };

    uint32_t aoff[2], boff[2];
    #pragma unroll
    for (int mt = 0; mt < 2; mt++)
        aoff[mt] = (uint32_t)((wm * 32 + mt * 16 + ((lane >> 3) & 1) * 8 + (lane & 7)) * 80
                              + (lane >> 4) * 16);
    #pragma unroll
    for (int nt = 0; nt < 2; nt++)
        boff[nt] = 5120u + (uint32_t)((wn * 32 + nt * 16 + ((lane >> 4) & 1) * 8 + (lane & 7)) * 80
                                      + ((lane >> 3) & 1) * 16);

    float acc[2][4][4];
    #pragma unroll
    for (int mt = 0; mt < 2; mt++)
        #pragma unroll
        for (int nb = 0; nb < 4; nb++)
            #pragma unroll
            for (int e = 0; e < 4; e++) acc[mt][nb][e] = 0.f;

    issue_stage(0, 0);
    issue_stage(1, 1);

    for (int kk = 0; kk < 16; kk++) {
        if (kk < 15) asm volatile("cp.async.wait_group 1;" ::: "memory");
        else         asm volatile("cp.async.wait_group 0;" ::: "memory");
        __syncthreads();

        if (kk + 2 < 16) issue_stage(kk + 2, (kk + 2) % 3);

        const uint32_t sa = sbase + (uint32_t)(kk % 3) * OSTAGE;

        #pragma unroll
        for (int ks = 0; ks < 2; ks++) {
            const uint32_t kso = (uint32_t)(ks * 32);
            uint32_t af[2][4], bfr[2][4];
            #pragma unroll
            for (int mt = 0; mt < 2; mt++)
                ldsm4(af[mt][0], af[mt][1], af[mt][2], af[mt][3], sa + aoff[mt] + kso);
            #pragma unroll
            for (int nt = 0; nt < 2; nt++)
                ldsm4(bfr[nt][0], bfr[nt][1], bfr[nt][2], bfr[nt][3], sa + boff[nt] + kso);

            #pragma unroll
            for (int mt = 0; mt < 2; mt++)
                #pragma unroll
                for (int nt = 0; nt < 2; nt++) {
                    mma_f16(acc[mt][2*nt][0], acc[mt][2*nt][1], acc[mt][2*nt][2], acc[mt][2*nt][3],
                            af[mt][0], af[mt][1], af[mt][2], af[mt][3],
                            bfr[nt][0], bfr[nt][1]);
                    mma_f16(acc[mt][2*nt+1][0], acc[mt][2*nt+1][1], acc[mt][2*nt+1][2], acc[mt][2*nt+1][3],
                            af[mt][0], af[mt][1], af[mt][2], af[mt][3],
                            bfr[nt][2], bfr[nt][3]);
                }
        }
    }

    const int r  = lane >> 2;
    const int cp = (lane & 3) * 2;
    #pragma unroll
    for (int mt = 0; mt < 2; mt++) {
        #pragma unroll
        for (int nb = 0; nb < 4; nb++) {
            const int cc = col0 + wn * 32 + nb * 8 + cp;
            const float bx = bias[cc], by = bias[cc + 1];
            const long r1 = row0 + wm * 32 + mt * 16 + r;
            *(float2*)(C + r1 * 512 + cc)       = make_float2(acc[mt][nb][0] + bx, acc[mt][nb][1] + by);
            *(float2*)(C + (r1 + 8) * 512 + cc) = make_float2(acc[mt][nb][2] + bx, acc[mt][nb][3] + by);
        }
    }
}

// ---------------- windowed attention: 8-way d-split, 256 threads ----------------
__constant__ int C_DF[14] = {-1,-1,-1,-1,-1,-1,-1,-1,-1, 0, 0, 0, 0, 0};
__constant__ int C_DH[14] = {-1,-1,-1, 0, 0, 0, 1, 1, 1,-1,-1,-1, 0, 0};
__constant__ int C_DW[14] = {-1, 0, 1,-1, 0, 1,-1, 0, 1,-1, 0, 1,-1, 0};

__global__ __launch_bounds__(256, 4)
void attn_kernel()
{
    __shared__ float qs[2112];
    __shared__ float ps[8][15][32];

    const int blk  = blockIdx.x;
    const int tid  = threadIdx.x;

    if (blk == 2048) {
        for (int e = tid; e < 1024; e += 256) {
            const int b = e >> 9, t = e & 511;
            const int h = t >> 6, d = t & 63;
            const float2 v = g_vtp[((long)(((b << 3) | h) * 32 + (d >> 1))) * NTOK];
            g_zh[(long)b * NTOK * 512 + t] = __float2half((d & 1) ? v.y : v.x);
        }
        return;
    }

    const int w    = tid >> 5;
    const int lane = tid & 31;
    const int grp  = blk & 127;
    const int bh   = blk >> 7;
    const int b    = bh >> 3;
    const int h    = bh & 7;
    const int i0   = grp * 32;
    const int f    = i0 >> 10;
    const int hh   = (i0 >> 5) & 31;
    const int i    = i0 + lane;

    {
        const int r = tid >> 3;
        const int c = (tid & 7) * 8;
        const int tk = min(i0 + r, NPOS - 1) + 1;
        const float* src = g_q + (long)(b * NTOK + tk) * 512 + h * 64 + c;
        float4 v0 = *(const float4*)(src);
        float4 v1 = *(const float4*)(src + 4);
        qs[r * 65 + c + 0] = v0.x; qs[r * 65 + c + 1] = v0.y;
        qs[r * 65 + c + 2] = v0.z; qs[r * 65 + c + 3] = v0.w;
        qs[r * 65 + c + 4] = v1.x; qs[r * 65 + c + 5] = v1.y;
        qs[r * 65 + c + 6] = v1.z; qs[r * 65 + c + 7] = v1.w;
    }
    __syncthreads();

    float q[8];
    #pragma unroll
    for (int j = 0; j < 8; j++) q[j] = qs[lane * 65 + w * 8 + j] * SCALE_Q;

    const float2* ktb = g_ktp + ((long)bh * 32 + w * 4) * NTOK;
    const float2* vtb = g_vtp + ((long)bh * 32 + w * 4) * NTOK;

    {   // BOS
        float a0 = 0.f, a1 = 0.f;
        #pragma unroll
        for (int dp = 0; dp < 4; dp++) {
            const float2 kk = ktb[(long)dp * NTOK];
            a0 += q[2 * dp]     * kk.x;
            a1 += q[2 * dp + 1] * kk.y;
        }
        ps[w][0][lane] = a0 + a1;
    }
    #pragma unroll
    for (int s = 0; s < 14; s++) {
        const int df = C_DF[s], dh = C_DH[s], dw = C_DW[s];
        const int off = df * 1024 + dh * 32 + dw;
        const int warp_ok = (f + df >= 0) && ((unsigned)(hh + dh) < 32u);
        float acc = 0.f;
        if (warp_ok) {
            const int t = min(max(i + off, 0), NPOS - 1) + 1;
            const float2* kp = ktb + t;
            float a0 = 0.f, a1 = 0.f;
            #pragma unroll
            for (int dp = 0; dp < 4; dp++) {
                const float2 kk = kp[(long)dp * NTOK];
                a0 += q[2 * dp]     * kk.x;
                a1 += q[2 * dp + 1] * kk.y;
            }
            acc = a0 + a1;
        }
        ps[w][s + 1][lane] = acc;
    }
    __syncthreads();

    const float NEG_INF = __int_as_float(0xff800000);
    float p[15];
    {
        #pragma unroll
        for (int s = 0; s < 15; s++) {
            float v = ps[0][s][lane];
            #pragma unroll
            for (int ww = 1; ww < 8; ww++) v += ps[ww][s][lane];
            p[s] = v;
        }
        #pragma unroll
        for (int s = 0; s < 14; s++) {
            const int df = C_DF[s], dh = C_DH[s], dw = C_DW[s];
            const int ok = (f + df >= 0) && ((unsigned)(hh + dh) < 32u)
                        && ((unsigned)(lane + dw) < 32u) && (i < NPOS);
            if (!ok) p[s + 1] = NEG_INF;
        }
        float m = p[0];
        #pragma unroll
        for (int s = 1; s < 15; s++) m = fmaxf(m, p[s]);
        float den = 0.f;
        #pragma unroll
        for (int s = 0; s < 15; s++) { p[s] = __expf(p[s] - m); den += p[s]; }
        const float inv = 1.f / den;
        #pragma unroll
        for (int s = 0; s < 15; s++) p[s] *= inv;
    }

    float o[8];
    #pragma unroll
    for (int d = 0; d < 8; d++) o[d] = 0.f;
    {   // BOS
        const float pw = p[0];
        #pragma unroll
        for (int dp = 0; dp < 4; dp++) {
            const float2 vv = vtb[(long)dp * NTOK];
            o[2 * dp]     += pw * vv.x;
            o[2 * dp + 1] += pw * vv.y;
        }
    }
    #pragma unroll
    for (int s = 0; s < 14; s++) {
        const int df = C_DF[s], dh = C_DH[s], dw = C_DW[s];
        const int warp_ok = (f + df >= 0) && ((unsigned)(hh + dh) < 32u);
        if (warp_ok) {
            const int off = df * 1024 + dh * 32 + dw;
            const int t = min(max(i + off, 0), NPOS - 1) + 1;
            const float pw = p[s + 1];
            const float2* vp = vtb + t;
            #pragma unroll
            for (int dp = 0; dp < 4; dp++) {
                const float2 vv = vp[(long)dp * NTOK];
                o[2 * dp]     += pw * vv.x;
                o[2 * dp + 1] += pw * vv.y;
            }
        }
    }
    __syncthreads();

    #pragma unroll
    for (int d = 0; d < 8; d++) qs[(w * 8 + d) * 33 + lane] = o[d];
    __syncthreads();

    {
        const int r = tid >> 3;
        const int c = (tid & 7) * 8;
        const int irow = i0 + r;
        if (irow < NPOS) {
            __half* dst = g_zh + (long)(b * NTOK + irow + 1) * 512 + h * 64 + c;
            #pragma unroll
            for (int j = 0; j < 8; j += 2) {
                const float x0 = qs[(c + j) * 33 + r];
                const float x1 = qs[(c + j + 1) * 33 + r];
                *(__half2*)(dst + j) = __floats2half2_rn(x0, x1);
            }
        }
    }
}

// ---------------- launch ----------------
extern "C" void kernel_launch(void* const* d_in, const int* in_sizes, int n_in,
                              void* d_out, int out_size)
{
    const float* x   = (const float*)d_in[0];
    const float* Wq  = (const float*)d_in[1];
    const float* Wkv = (const float*)d_in[2];
    const float* Wo  = (const float*)d_in[3];
    const float* bo  = (const float*)d_in[4];
    float* out = (float*)d_out;

    __half *xh, *wqkvt, *wot, *zh;
    cudaGetSymbolAddress((void**)&xh,    g_xh);
    cudaGetSymbolAddress((void**)&zh,    g_zh);
    cudaGetSymbolAddress((void**)&wqkvt, g_wqkvt);
    cudaGetSymbolAddress((void**)&wot,   g_wot);

    cudaFuncSetAttribute(tgemm_qkv, cudaFuncAttributeMaxDynamicSharedMemorySize, HSMEM);
    cudaFuncSetAttribute(tgemm_out, cudaFuncAttributeMaxDynamicSharedMemorySize, OSMEM);

    // 0) fused prologue
    prep_kernel<<<4096 + 256 + 512 + 256, 256>>>(x, Wq, Wkv, Wo);

    // 1) fused QKV projection with coalesced routing epilogue (k-chunk 32)
    tgemm_qkv<<<dim3(QKVN / 128, MROWS / 128), 128, HSMEM>>>(xh, wqkvt);

    // 2) windowed causal attention + fused BOS rows
    attn_kernel<<<2049, 256>>>();

    // 3) output projection + bias (64x64 tiles, k-chunk 32)
    tgemm_out<<<dim3(512 / 64, MROWS / 64), 128, OSMEM>>>(zh, wot, bo, out);
}